// round 15
// baseline (speedup 1.0000x reference)
#include <cuda_runtime.h>
#include <cuda_fp16.h>
#include <cstdint>
#include <math.h>

#define B_  2
#define L_  2048
#define C_  1024
#define H_  16
#define HD_ 64
#define M_  (B_*L_)      // 4096
#define BH_ (B_*H_)      // 32

// ---------------- scratch (device globals: allocation-free rule) -----------
__device__ __half g_xh [M_*C_];                      // x fp16
__device__ __half g_wh [3*C_*C_];                    // w_qkv fp16
__device__ __half g_pwh[C_*C_];                      // w_proj fp16
__device__ __half g_b16[L_*L_];                      // attn_bias fp16
__device__ float  g_v[BH_*L_*HD_];
__device__ __half g_qh[BH_*L_*HD_];                  // normalized+scaled q (fp16)
__device__ __half g_kh[BH_*L_*HD_];                  // normalized k (fp16)
__device__ __half g_vth[BH_*HD_*L_];                 // V^T fp16 [bh][hd][l]
__device__ __half g_aoh[M_*C_];                      // attn out fp16

// ---------------- asm helpers ----------------------------------------------
__device__ __forceinline__ uint32_t smem_u32(const void* p){
    uint32_t a;
    asm("{ .reg .u64 t; cvta.to.shared.u64 t, %1; cvt.u32.u64 %0, t; }" : "=r"(a) : "l"(p));
    return a;
}
#define LDSM4(r0,r1,r2,r3,addr) asm volatile( \
    "ldmatrix.sync.aligned.m8n8.x4.shared.b16 {%0,%1,%2,%3}, [%4];" \
    : "=r"(r0),"=r"(r1),"=r"(r2),"=r"(r3) : "r"(addr))

#define MMA(d, a, b0v, b1v) asm volatile( \
    "mma.sync.aligned.m16n8k16.row.col.f32.f16.f16.f32 " \
    "{%0,%1,%2,%3}, {%4,%5,%6,%7}, {%8,%9}, {%0,%1,%2,%3};" \
    : "+f"((d)[0]),"+f"((d)[1]),"+f"((d)[2]),"+f"((d)[3]) \
    : "r"((a)[0]),"r"((a)[1]),"r"((a)[2]),"r"((a)[3]), "r"(b0v),"r"(b1v))

#define CP16(dst,src) asm volatile("cp.async.cg.shared.global [%0], [%1], 16;" :: "r"(dst), "l"(src))
#define CPCOMMIT()    asm volatile("cp.async.commit_group;" ::: "memory")
#define CPWAIT0()     asm volatile("cp.async.wait_group 0;" ::: "memory")
#define CPWAIT1()     asm volatile("cp.async.wait_group 1;" ::: "memory")

__device__ __forceinline__ uint32_t packh2(float a, float b){
    __half2 t = __floats2half2_rn(a, b);
    return *reinterpret_cast<uint32_t*>(&t);
}

// ---------------- fused fp32 -> fp16 convert (x, w_qkv, w_proj, bias) -------
#define SEG0 (M_*C_/4)          // 1048576
#define SEG1 (3*C_*C_/4)        // 786432
#define SEG2 (C_*C_/4)          // 262144
#define SEG3 (L_*L_/4)          // 1048576
__global__ __launch_bounds__(256) void cvt_all(const float* __restrict__ x,
                                               const float* __restrict__ wqkv,
                                               const float* __restrict__ wproj,
                                               const float* __restrict__ bias){
    int i = blockIdx.x * 256 + threadIdx.x;
    const float* s; __half* d; int j;
    if (i < SEG0)                    { s = x;     d = g_xh;  j = i; }
    else if (i < SEG0+SEG1)          { s = wqkv;  d = g_wh;  j = i - SEG0; }
    else if (i < SEG0+SEG1+SEG2)     { s = wproj; d = g_pwh; j = i - SEG0 - SEG1; }
    else if (i < SEG0+SEG1+SEG2+SEG3){ s = bias;  d = g_b16; j = i - SEG0 - SEG1 - SEG2; }
    else return;
    float4 v = ((const float4*)s)[j];
    ((__half2*)d)[2*j]   = __floats2half2_rn(v.x, v.y);
    ((__half2*)d)[2*j+1] = __floats2half2_rn(v.z, v.w);
}

// ---------------- fp16 mma.sync GEMM -----------------------------------------
// out[m,n] = sum_k A[m,k]*W[n,k]. Block 128x128, BK=32, 8 warps (4M x 2N),
// warp tile 32x64. cp.async 3-stage (wait_group 1 hides L2 latency). 2 CTAs/SM.
template<int MODE>
__global__ __launch_bounds__(256, 2) void gemm_mma(const float* __restrict__ bias0,
                                                   const float* __restrict__ bias1,
                                                   const float* __restrict__ scale_mul,
                                                   float* __restrict__ out)
{
    extern __shared__ char smem[];
    const uint32_t sb = smem_u32(smem);
    const int tid = threadIdx.x;
    const int w = tid >> 5, lane = tid & 31;
    const int wm = w & 3, wn = w >> 2;
    const int g = lane >> 2, c = lane & 3;
    const int m0 = blockIdx.y * 128, n0 = blockIdx.x * 128;

    const __half* Ah = (MODE==0) ? g_xh : g_aoh;
    const __half* Bh = (MODE==0) ? g_wh : g_pwh;

    const uint32_t SZ  = 10240;   // one [128][40] half tile
    const uint32_t BUF = 2*SZ;    // 20480 per stage

    const int lr = tid >> 2;
    const int lc = (tid & 3) << 3;
    const size_t offA = (size_t)(m0 + lr) * C_ + lc;
    const size_t offB = (size_t)(n0 + lr) * C_ + lc;
    const uint32_t sdst = (uint32_t)(lr * 40 + lc) * 2;

    float acc[2][8][4];
    #pragma unroll
    for (int i=0;i<2;i++)
        #pragma unroll
        for (int j=0;j<8;j++)
            #pragma unroll
            for (int k=0;k<4;k++) acc[i][j][k]=0.f;

    // prefetch kt=0,1 into stages 0,1
    #pragma unroll
    for (int s=0;s<2;s++){
        uint32_t bb = sb + (uint32_t)s*BUF;
        #pragma unroll
        for (int i=0;i<2;i++){
            uint32_t d = bb + sdst + i*5120;
            CP16(d + 0*SZ, Ah + offA + (size_t)i*64*C_ + s*32);
            CP16(d + 1*SZ, Bh + offB + (size_t)i*64*C_ + s*32);
        }
        CPCOMMIT();
    }
    CPWAIT1(); __syncthreads();     // stage 0 ready

    #pragma unroll 1
    for (int kt = 0; kt < 32; kt++) {
        if (kt + 2 < 32) {
            uint32_t bb = sb + (uint32_t)((kt+2)%3)*BUF;
            #pragma unroll
            for (int i=0;i<2;i++){
                uint32_t d = bb + sdst + i*5120;
                CP16(d + 0*SZ, Ah + offA + (size_t)i*64*C_ + (kt+2)*32);
                CP16(d + 1*SZ, Bh + offB + (size_t)i*64*C_ + (kt+2)*32);
            }
            CPCOMMIT();
        }
        const uint32_t base = sb + (uint32_t)(kt%3)*BUF;
        #pragma unroll
        for (int ks=0; ks<2; ks++){
            uint32_t afh[2][4];
            #pragma unroll
            for (int mf=0; mf<2; mf++){
                uint32_t ar = (uint32_t)((wm*32 + mf*16 + (lane&15))*40 + ks*16 + (lane>>4)*8)*2;
                LDSM4(afh[mf][0],afh[mf][1],afh[mf][2],afh[mf][3], base + 0*SZ + ar);
            }
            #pragma unroll
            for (int nf2=0; nf2<4; nf2++){
                uint32_t br = (uint32_t)((wn*64 + nf2*16 + (lane&7) + ((lane>>4)<<3))*40
                                         + ks*16 + (((lane>>3)&1)<<3))*2;
                uint32_t bh0,bh1,bh2,bh3;
                LDSM4(bh0,bh1,bh2,bh3, base + 1*SZ + br);
                #pragma unroll
                for (int mf=0; mf<2; mf++){
                    MMA(acc[mf][2*nf2],   afh[mf], bh0,bh1);
                    MMA(acc[mf][2*nf2+1], afh[mf], bh2,bh3);
                }
            }
        }
        if (kt < 31){
            if (kt < 30) CPWAIT1(); else CPWAIT0();
            __syncthreads();
        }
    }

    // ---- epilogue ----
    if (MODE == 0){
        const int which = n0 >> 10;                 // 0=q 1=k 2=v
        const int h = ((n0 & (C_-1)) + wn*64) >> 6; // head (warp-uniform)
        if (which == 2){
            #pragma unroll
            for (int mf=0; mf<2; mf++)
            #pragma unroll
            for (int hh=0; hh<2; hh++){
                int m = m0 + wm*32 + mf*16 + g + hh*8;
                int b = m >> 11, l = m & (L_-1);
                size_t rowb = (((size_t)(b*H_+h))*L_ + l)*HD_;
                #pragma unroll
                for (int nf=0; nf<8; nf++){
                    int hd = nf*8 + 2*c;
                    int rem = (n0 & (C_-1)) + wn*64 + hd;
                    float2 o;
                    o.x = acc[mf][nf][hh*2+0] + bias1[rem];
                    o.y = acc[mf][nf][hh*2+1] + bias1[rem+1];
                    *(float2*)&g_v[rowb + hd] = o;
                }
            }
        } else {
            __half* dst = (which == 0) ? g_qh : g_kh;
            float smul = 1.f;
            if (which == 0) smul = __expf(fminf(scale_mul[h], 4.6051702f));
            #pragma unroll
            for (int mf=0; mf<2; mf++)
            #pragma unroll
            for (int hh=0; hh<2; hh++){
                int m = m0 + wm*32 + mf*16 + g + hh*8;
                int b = m >> 11, l = m & (L_-1);
                float vals[16];
                float ss = 0.f;
                #pragma unroll
                for (int nf=0; nf<8; nf++){
                    int rem = (n0 & (C_-1)) + wn*64 + nf*8 + 2*c;
                    float vx = acc[mf][nf][hh*2+0];
                    float vy = acc[mf][nf][hh*2+1];
                    if (which == 0){ vx += bias0[rem]; vy += bias0[rem+1]; }
                    vals[2*nf] = vx; vals[2*nf+1] = vy;
                    ss += vx*vx + vy*vy;
                }
                ss += __shfl_xor_sync(0xffffffffu, ss, 1);
                ss += __shfl_xor_sync(0xffffffffu, ss, 2);
                float s = rsqrtf(ss) * smul;
                size_t rowb = (((size_t)(b*H_+h))*L_ + l)*HD_;
                #pragma unroll
                for (int nf=0; nf<8; nf++)
                    *(__half2*)&dst[rowb + nf*8 + 2*c] =
                        __floats2half2_rn(vals[2*nf]*s, vals[2*nf+1]*s);
            }
        }
    } else {
        #pragma unroll
        for (int mf=0; mf<2; mf++)
        #pragma unroll
        for (int hh=0; hh<2; hh++){
            int m = m0 + wm*32 + mf*16 + g + hh*8;
            #pragma unroll
            for (int nf=0; nf<8; nf++){
                int n = n0 + wn*64 + nf*8 + 2*c;
                float2 o;
                o.x = acc[mf][nf][hh*2+0] + bias0[n];
                o.y = acc[mf][nf][hh*2+1] + bias0[n+1];
                *(float2*)&out[(size_t)m*C_ + n] = o;
            }
        }
    }
}

// ---------------- transpose V [bh][l][hd] -> fp16 [bh][hd][l] ----------------
__global__ void vtrans_kernel()
{
    __shared__ float t[32][33];
    const int bh = blockIdx.z, l0 = blockIdx.x * 32, d0 = blockIdx.y * 32;
    const int tx = threadIdx.x, ty = threadIdx.y;
    for (int i = ty; i < 32; i += 8)
        t[i][tx] = g_v[((size_t)bh * L_ + l0 + i) * HD_ + d0 + tx];
    __syncthreads();
    for (int i = ty; i < 32; i += 8)
        g_vth[((size_t)bh * HD_ + d0 + i) * L_ + l0 + tx] = __float2half_rn(t[tx][i]);
}

// ---------------- fused FA2-style attention ----------------------------------
// CTA = 128 q rows x one bh; 8 warps x 16-row strips; 64-key chunks (32 iters),
// cp.async 3-stage; fp16 bias; 2 CTAs/SM. Bounded scores -> softmax w/o
// max-sub; O and lsum persist in registers across all chunks.
__device__ __forceinline__ void attn_load_chunk(uint32_t dstbase, int bh, int k0, int tid){
    #pragma unroll
    for (int i=0;i<2;i++){                     // K chunk: 64 keys x 64 hd
        int idx = i*256 + tid;
        int r = idx >> 3, cg = (idx & 7) << 3;
        CP16(dstbase + (uint32_t)(r*72 + cg)*2,
             g_kh + ((size_t)bh*L_ + k0 + r)*HD_ + cg);
    }
    #pragma unroll
    for (int i=0;i<2;i++){                     // Vt: 64 hd x 64 keys
        int idx = i*256 + tid;
        int d = idx >> 3, cg = (idx & 7) << 3;
        CP16(dstbase + 9216 + (uint32_t)(d*72 + cg)*2,
             g_vth + ((size_t)bh*HD_ + d)*L_ + k0 + cg);
    }
}

__global__ __launch_bounds__(256, 2) void attn_mma()
{
    extern __shared__ char smem[];
    const uint32_t sb = smem_u32(smem);
    const int tid = threadIdx.x, w = tid >> 5, lane = tid & 31;
    const int g = lane >> 2, c = lane & 3;
    const int bh = blockIdx.y, q0 = blockIdx.x * 128;
    // smem: Q[128][72] @0 (18432B); 3 chunk stages of K[64][72]+V[64][72]
    const uint32_t CB0 = 18432, CSZ = 18432;

    #pragma unroll
    for (int i=0;i<4;i++){                     // Q plain load
        int idx = i*256 + tid;
        int r = idx >> 3, cg = (idx & 7) << 3;
        uint4 v = *(const uint4*)(g_qh + ((size_t)bh*L_ + q0 + r)*HD_ + cg);
        *(uint4*)(smem + (r*72 + cg)*2) = v;
    }
    attn_load_chunk(sb + CB0 + 0*CSZ, bh, 0, tid);  CPCOMMIT();
    attn_load_chunk(sb + CB0 + 1*CSZ, bh, 64, tid); CPCOMMIT();
    CPWAIT1(); __syncthreads();                // chunk 0 + Q ready

    uint32_t qf[4][4];
    #pragma unroll
    for (int ks=0; ks<4; ks++){
        uint32_t a = sb + (uint32_t)((w*16 + (lane&15))*72 + ks*16 + (lane>>4)*8)*2;
        LDSM4(qf[ks][0],qf[ks][1],qf[ks][2],qf[ks][3], a);
    }

    float Of[8][4];
    #pragma unroll
    for (int i=0;i<8;i++){ Of[i][0]=Of[i][1]=Of[i][2]=Of[i][3]=0.f; }
    float ls0 = 0.f, ls1 = 0.f;
    const __half* bp0 = g_b16 + (size_t)(q0 + w*16 + g) * L_;

    #pragma unroll 1
    for (int ch = 0; ch < 32; ch++){
        if (ch + 2 < 32){
            attn_load_chunk(sb + CB0 + (uint32_t)((ch+2)%3)*CSZ, bh, (ch+2)*64, tid);
            CPCOMMIT();
        }
        const uint32_t kb = sb + CB0 + (uint32_t)(ch%3)*CSZ;

        float sacc[8][4];
        #pragma unroll
        for (int i=0;i<8;i++){ sacc[i][0]=sacc[i][1]=sacc[i][2]=sacc[i][3]=0.f; }
        #pragma unroll
        for (int ks=0; ks<4; ks++){
            #pragma unroll
            for (int nf2=0; nf2<4; nf2++){
                uint32_t a = kb + (uint32_t)((nf2*16 + (lane&7) + ((lane>>4)<<3))*72
                                             + ks*16 + (((lane>>3)&1)<<3))*2;
                uint32_t b0,b1,b2,b3;
                LDSM4(b0,b1,b2,b3, a);
                MMA(sacc[2*nf2],   qf[ks], b0,b1);
                MMA(sacc[2*nf2+1], qf[ks], b2,b3);
            }
        }
        const int k0 = ch*64;
        #pragma unroll
        for (int nf=0; nf<8; nf++){            // softmax (bounded scores)
            float2 bb0 = __half22float2(*(const __half2*)(bp0 + k0 + nf*8 + 2*c));
            float2 bb1 = __half22float2(*(const __half2*)(bp0 + 8*L_ + k0 + nf*8 + 2*c));
            sacc[nf][0] = __expf(sacc[nf][0] + bb0.x);
            sacc[nf][1] = __expf(sacc[nf][1] + bb0.y);
            sacc[nf][2] = __expf(sacc[nf][2] + bb1.x);
            sacc[nf][3] = __expf(sacc[nf][3] + bb1.y);
            ls0 += sacc[nf][0] + sacc[nf][1];
            ls1 += sacc[nf][2] + sacc[nf][3];
        }
        #pragma unroll
        for (int ks=0; ks<4; ks++){            // O += P V
            uint32_t pa[4];
            pa[0] = packh2(sacc[2*ks][0],   sacc[2*ks][1]);
            pa[1] = packh2(sacc[2*ks][2],   sacc[2*ks][3]);
            pa[2] = packh2(sacc[2*ks+1][0], sacc[2*ks+1][1]);
            pa[3] = packh2(sacc[2*ks+1][2], sacc[2*ks+1][3]);
            #pragma unroll
            for (int nf2=0; nf2<4; nf2++){
                uint32_t ro = (uint32_t)((nf2*16 + (lane&7) + ((lane>>4)<<3))*72
                                         + ks*16 + (((lane>>3)&1)<<3))*2;
                uint32_t h0,h1,h2,h3;
                LDSM4(h0,h1,h2,h3, kb + 9216 + ro);
                MMA(Of[2*nf2],   pa, h0,h1);
                MMA(Of[2*nf2+1], pa, h2,h3);
            }
        }
        if (ch < 31){
            if (ch < 30) CPWAIT1(); else CPWAIT0();
            __syncthreads();
        }
    }

    ls0 += __shfl_xor_sync(0xffffffffu, ls0, 1);
    ls0 += __shfl_xor_sync(0xffffffffu, ls0, 2);
    ls1 += __shfl_xor_sync(0xffffffffu, ls1, 1);
    ls1 += __shfl_xor_sync(0xffffffffu, ls1, 2);
    const float i0 = 1.f/ls0, i1 = 1.f/ls1;
    const int b = bh >> 4, h = bh & 15;
    const int lr = q0 + w*16 + g;
    #pragma unroll
    for (int nf=0; nf<8; nf++){
        int col = h*64 + nf*8 + 2*c;
        size_t o0 = ((size_t)b*L_ + lr)*C_ + col;
        size_t o1 = o0 + (size_t)8*C_;
        *(__half2*)&g_aoh[o0] = __floats2half2_rn(Of[nf][0]*i0, Of[nf][1]*i0);
        *(__half2*)&g_aoh[o1] = __floats2half2_rn(Of[nf][2]*i1, Of[nf][3]*i1);
    }
}

// ---------------------------------------------------------------------------
extern "C" void kernel_launch(void* const* d_in, const int* in_sizes, int n_in,
                              void* d_out, int out_size)
{
    (void)in_sizes; (void)n_in; (void)out_size;
    const float* x         = (const float*)d_in[0];
    const float* attn_bias = (const float*)d_in[1];
    const float* w_qkv     = (const float*)d_in[2];
    const float* q_bias    = (const float*)d_in[3];
    const float* v_bias    = (const float*)d_in[4];
    const float* scale_mul = (const float*)d_in[5];
    const float* w_proj    = (const float*)d_in[6];
    const float* b_proj    = (const float*)d_in[7];
    float* out = (float*)d_out;

    const int GEMM_SMEM = 61440;   // 3 stages x 20480
    const int ATT_SMEM  = 73728;   // Q 18432 + 3 x 18432
    cudaFuncSetAttribute(gemm_mma<0>, cudaFuncAttributeMaxDynamicSharedMemorySize, GEMM_SMEM);
    cudaFuncSetAttribute(gemm_mma<1>, cudaFuncAttributeMaxDynamicSharedMemorySize, GEMM_SMEM);
    cudaFuncSetAttribute(attn_mma,    cudaFuncAttributeMaxDynamicSharedMemorySize, ATT_SMEM);

    // 0) convert all fp32 inputs to fp16 in one launch
    const int NCVT = SEG0 + SEG1 + SEG2 + SEG3;
    cvt_all<<<(NCVT + 255)/256, 256>>>(x, w_qkv, w_proj, attn_bias);

    // 1) QKV projection + fused q/k L2-norm
    gemm_mma<0><<<dim3(3*C_/128, M_/128), 256, GEMM_SMEM>>>(q_bias, v_bias, scale_mul, nullptr);

    // 2) transpose V -> fp16
    vtrans_kernel<<<dim3(L_/32, HD_/32, BH_), dim3(32, 8)>>>();

    // 3) fused attention
    attn_mma<<<dim3(L_/128, BH_), 256, ATT_SMEM>>>();

    // 4) output projection
    gemm_mma<1><<<dim3(C_/128, M_/128), 256, GEMM_SMEM>>>(b_proj, nullptr, nullptr, out);
}

// round 17
// speedup vs baseline: 1.0823x; 1.0823x over previous
#include <cuda_runtime.h>
#include <cuda_fp16.h>
#include <cstdint>
#include <math.h>

#define B_  2
#define L_  2048
#define C_  1024
#define H_  16
#define HD_ 64
#define M_  (B_*L_)      // 4096
#define BH_ (B_*H_)      // 32

// ---------------- scratch (device globals: allocation-free rule) -----------
__device__ __half g_xh [M_*C_];                      // x fp16
__device__ __half g_wh [3*C_*C_];                    // w_qkv fp16
__device__ __half g_pwh[C_*C_];                      // w_proj fp16
__device__ __half g_qh[BH_*L_*HD_];                  // normalized+scaled q (fp16)
__device__ __half g_kh[BH_*L_*HD_];                  // normalized k (fp16)
__device__ __half g_vth[BH_*HD_*L_];                 // V^T fp16 [bh][hd][l]
__device__ __half g_aoh[M_*C_];                      // attn out fp16

// ---------------- asm helpers ----------------------------------------------
__device__ __forceinline__ uint32_t smem_u32(const void* p){
    uint32_t a;
    asm("{ .reg .u64 t; cvta.to.shared.u64 t, %1; cvt.u32.u64 %0, t; }" : "=r"(a) : "l"(p));
    return a;
}
#define LDSM4(r0,r1,r2,r3,addr) asm volatile( \
    "ldmatrix.sync.aligned.m8n8.x4.shared.b16 {%0,%1,%2,%3}, [%4];" \
    : "=r"(r0),"=r"(r1),"=r"(r2),"=r"(r3) : "r"(addr))

#define MMA(d, a, b0v, b1v) asm volatile( \
    "mma.sync.aligned.m16n8k16.row.col.f32.f16.f16.f32 " \
    "{%0,%1,%2,%3}, {%4,%5,%6,%7}, {%8,%9}, {%0,%1,%2,%3};" \
    : "+f"((d)[0]),"+f"((d)[1]),"+f"((d)[2]),"+f"((d)[3]) \
    : "r"((a)[0]),"r"((a)[1]),"r"((a)[2]),"r"((a)[3]), "r"(b0v),"r"(b1v))

#define CP16(dst,src) asm volatile("cp.async.cg.shared.global [%0], [%1], 16;" :: "r"(dst), "l"(src))
#define CPCOMMIT()    asm volatile("cp.async.commit_group;" ::: "memory")
#define CPWAIT0()     asm volatile("cp.async.wait_group 0;" ::: "memory")
#define CPWAIT1()     asm volatile("cp.async.wait_group 1;" ::: "memory")

__device__ __forceinline__ uint32_t packh2(float a, float b){
    __half2 t = __floats2half2_rn(a, b);
    return *reinterpret_cast<uint32_t*>(&t);
}

// ---------------- fused fp32 -> fp16 convert (x, w_qkv, w_proj) -------------
#define SEG0 (M_*C_/4)          // 1048576
#define SEG1 (3*C_*C_/4)        // 786432
#define SEG2 (C_*C_/4)          // 262144
__global__ __launch_bounds__(256) void cvt_all(const float* __restrict__ x,
                                               const float* __restrict__ wqkv,
                                               const float* __restrict__ wproj){
    int i = blockIdx.x * 256 + threadIdx.x;
    const float* s; __half* d; int j;
    if (i < SEG0)                { s = x;     d = g_xh;  j = i; }
    else if (i < SEG0+SEG1)      { s = wqkv;  d = g_wh;  j = i - SEG0; }
    else if (i < SEG0+SEG1+SEG2) { s = wproj; d = g_pwh; j = i - SEG0 - SEG1; }
    else return;
    float4 v = ((const float4*)s)[j];
    ((__half2*)d)[2*j]   = __floats2half2_rn(v.x, v.y);
    ((__half2*)d)[2*j+1] = __floats2half2_rn(v.z, v.w);
}

// ---------------- fp16 mma.sync GEMM -----------------------------------------
// out[m,n] = sum_k A[m,k]*W[n,k]. Block 128x128, BK=32, 8 warps (4M x 2N),
// warp tile 32x64. cp.async 3-stage. 2 CTAs/SM.
// MODE 0: qkv epilogue — q/k rows L2-normalized -> fp16 g_qh/g_kh;
//         v (+v_bias) transposed via smem -> fp16 g_vth (fused vtrans).
// MODE 1: proj epilogue — +b_proj, write d_out.
template<int MODE>
__global__ __launch_bounds__(256, 2) void gemm_mma(const float* __restrict__ bias0,
                                                   const float* __restrict__ bias1,
                                                   const float* __restrict__ scale_mul,
                                                   float* __restrict__ out)
{
    extern __shared__ char smem[];
    const uint32_t sb = smem_u32(smem);
    const int tid = threadIdx.x;
    const int w = tid >> 5, lane = tid & 31;
    const int wm = w & 3, wn = w >> 2;
    const int g = lane >> 2, c = lane & 3;
    const int m0 = blockIdx.y * 128, n0 = blockIdx.x * 128;

    const __half* Ah = (MODE==0) ? g_xh : g_aoh;
    const __half* Bh = (MODE==0) ? g_wh : g_pwh;

    const uint32_t SZ  = 10240;   // one [128][40] half tile
    const uint32_t BUF = 2*SZ;    // 20480 per stage

    const int lr = tid >> 2;
    const int lc = (tid & 3) << 3;
    const size_t offA = (size_t)(m0 + lr) * C_ + lc;
    const size_t offB = (size_t)(n0 + lr) * C_ + lc;
    const uint32_t sdst = (uint32_t)(lr * 40 + lc) * 2;

    float acc[2][8][4];
    #pragma unroll
    for (int i=0;i<2;i++)
        #pragma unroll
        for (int j=0;j<8;j++)
            #pragma unroll
            for (int k=0;k<4;k++) acc[i][j][k]=0.f;

    #pragma unroll
    for (int s=0;s<2;s++){
        uint32_t bb = sb + (uint32_t)s*BUF;
        #pragma unroll
        for (int i=0;i<2;i++){
            uint32_t d = bb + sdst + i*5120;
            CP16(d + 0*SZ, Ah + offA + (size_t)i*64*C_ + s*32);
            CP16(d + 1*SZ, Bh + offB + (size_t)i*64*C_ + s*32);
        }
        CPCOMMIT();
    }
    CPWAIT1(); __syncthreads();

    #pragma unroll 1
    for (int kt = 0; kt < 32; kt++) {
        if (kt + 2 < 32) {
            uint32_t bb = sb + (uint32_t)((kt+2)%3)*BUF;
            #pragma unroll
            for (int i=0;i<2;i++){
                uint32_t d = bb + sdst + i*5120;
                CP16(d + 0*SZ, Ah + offA + (size_t)i*64*C_ + (kt+2)*32);
                CP16(d + 1*SZ, Bh + offB + (size_t)i*64*C_ + (kt+2)*32);
            }
            CPCOMMIT();
        }
        const uint32_t base = sb + (uint32_t)(kt%3)*BUF;
        #pragma unroll
        for (int ks=0; ks<2; ks++){
            uint32_t afh[2][4];
            #pragma unroll
            for (int mf=0; mf<2; mf++){
                uint32_t ar = (uint32_t)((wm*32 + mf*16 + (lane&15))*40 + ks*16 + (lane>>4)*8)*2;
                LDSM4(afh[mf][0],afh[mf][1],afh[mf][2],afh[mf][3], base + 0*SZ + ar);
            }
            #pragma unroll
            for (int nf2=0; nf2<4; nf2++){
                uint32_t br = (uint32_t)((wn*64 + nf2*16 + (lane&7) + ((lane>>4)<<3))*40
                                         + ks*16 + (((lane>>3)&1)<<3))*2;
                uint32_t bh0,bh1,bh2,bh3;
                LDSM4(bh0,bh1,bh2,bh3, base + 1*SZ + br);
                #pragma unroll
                for (int mf=0; mf<2; mf++){
                    MMA(acc[mf][2*nf2],   afh[mf], bh0,bh1);
                    MMA(acc[mf][2*nf2+1], afh[mf], bh2,bh3);
                }
            }
        }
        if (kt < 31){
            if (kt < 30) CPWAIT1(); else CPWAIT0();
            __syncthreads();
        }
    }

    // ---- epilogue ----
    if (MODE == 0){
        const int which = n0 >> 10;                 // 0=q 1=k 2=v
        const int h = ((n0 & (C_-1)) + wn*64) >> 6; // head (warp-uniform)
        if (which == 2){
            // V: add bias, transpose 128x128 via smem, store fp16 [bh][hd][l]
            __syncthreads();                        // all smem reads done
            __half* t = (__half*)smem;              // [128][136]
            #pragma unroll
            for (int mf=0; mf<2; mf++)
            #pragma unroll
            for (int hh=0; hh<2; hh++){
                int ml = wm*32 + mf*16 + g + hh*8;  // local l
                #pragma unroll
                for (int nf=0; nf<8; nf++){
                    int nl = wn*64 + nf*8 + 2*c;    // local hd (2 heads span)
                    int rem = (n0 & (C_-1)) + nl;
                    t[(nl+0)*136 + ml] = __float2half_rn(acc[mf][nf][hh*2+0] + bias1[rem]);
                    t[(nl+1)*136 + ml] = __float2half_rn(acc[mf][nf][hh*2+1] + bias1[rem+1]);
                }
            }
            __syncthreads();
            const int b = m0 >> 11;
            const int l0 = m0 & (L_-1);
            const int r = tid >> 1, part = tid & 1;
            const int hh2 = ((n0 & (C_-1)) >> 6) + (r >> 6);
            const int hd  = r & 63;
            const size_t dstb = ((size_t)(b*H_ + hh2)*HD_ + hd)*L_ + l0 + part*64;
            const __half* srcr = t + r*136 + part*64;
            #pragma unroll
            for (int j=0;j<8;j++)
                *(uint4*)(g_vth + dstb + j*8) = *(const uint4*)(srcr + j*8);
        } else {
            __half* dst = (which == 0) ? g_qh : g_kh;
            float smul = 1.f;
            if (which == 0) smul = __expf(fminf(scale_mul[h], 4.6051702f));
            #pragma unroll
            for (int mf=0; mf<2; mf++)
            #pragma unroll
            for (int hh=0; hh<2; hh++){
                int m = m0 + wm*32 + mf*16 + g + hh*8;
                int b = m >> 11, l = m & (L_-1);
                float vals[16];
                float ss = 0.f;
                #pragma unroll
                for (int nf=0; nf<8; nf++){
                    int rem = (n0 & (C_-1)) + wn*64 + nf*8 + 2*c;
                    float vx = acc[mf][nf][hh*2+0];
                    float vy = acc[mf][nf][hh*2+1];
                    if (which == 0){ vx += bias0[rem]; vy += bias0[rem+1]; }
                    vals[2*nf] = vx; vals[2*nf+1] = vy;
                    ss += vx*vx + vy*vy;
                }
                ss += __shfl_xor_sync(0xffffffffu, ss, 1);
                ss += __shfl_xor_sync(0xffffffffu, ss, 2);
                float s = rsqrtf(ss) * smul;
                size_t rowb = (((size_t)(b*H_+h))*L_ + l)*HD_;
                #pragma unroll
                for (int nf=0; nf<8; nf++)
                    *(__half2*)&dst[rowb + nf*8 + 2*c] =
                        __floats2half2_rn(vals[2*nf]*s, vals[2*nf+1]*s);
            }
        }
    } else {
        #pragma unroll
        for (int mf=0; mf<2; mf++)
        #pragma unroll
        for (int hh=0; hh<2; hh++){
            int m = m0 + wm*32 + mf*16 + g + hh*8;
            #pragma unroll
            for (int nf=0; nf<8; nf++){
                int n = n0 + wn*64 + nf*8 + 2*c;
                float2 o;
                o.x = acc[mf][nf][hh*2+0] + bias0[n];
                o.y = acc[mf][nf][hh*2+1] + bias0[n+1];
                *(float2*)&out[(size_t)m*C_ + n] = o;
            }
        }
    }
}

// ---------------- fused FA2-style attention ----------------------------------
// CTA = 128 q rows x one bh; 4 warps x 32-row strips (K/V fragments shared by
// 2 row-blocks per warp -> half the LDSM traffic per MMA). 64-key chunks,
// cp.async 3-stage, fp32 bias, 2 CTAs/SM. Bounded scores -> softmax w/o
// max-sub; O and lsum persist in registers across all chunks.
__device__ __forceinline__ void attn_load_chunk(uint32_t dstbase, int bh, int k0, int tid){
    #pragma unroll
    for (int i=0;i<4;i++){                     // K chunk: 64 keys x 64 hd
        int idx = i*128 + tid;
        int r = idx >> 3, cg = (idx & 7) << 3;
        CP16(dstbase + (uint32_t)(r*72 + cg)*2,
             g_kh + ((size_t)bh*L_ + k0 + r)*HD_ + cg);
    }
    #pragma unroll
    for (int i=0;i<4;i++){                     // Vt: 64 hd x 64 keys
        int idx = i*128 + tid;
        int d = idx >> 3, cg = (idx & 7) << 3;
        CP16(dstbase + 9216 + (uint32_t)(d*72 + cg)*2,
             g_vth + ((size_t)bh*HD_ + d)*L_ + k0 + cg);
    }
}

__global__ __launch_bounds__(128, 2) void attn_mma(const float* __restrict__ bias)
{
    extern __shared__ char smem[];
    const uint32_t sb = smem_u32(smem);
    const int tid = threadIdx.x, w = tid >> 5, lane = tid & 31;
    const int g = lane >> 2, c = lane & 3;
    const int bh = blockIdx.y, q0 = blockIdx.x * 128;
    // smem: Q[128][72] @0 (18432B); 3 chunk stages of K[64][72]+V[64][72]
    const uint32_t CB0 = 18432, CSZ = 18432;

    #pragma unroll
    for (int i=0;i<8;i++){                     // Q plain load
        int idx = i*128 + tid;
        int r = idx >> 3, cg = (idx & 7) << 3;
        uint4 v = *(const uint4*)(g_qh + ((size_t)bh*L_ + q0 + r)*HD_ + cg);
        *(uint4*)(smem + (r*72 + cg)*2) = v;
    }
    attn_load_chunk(sb + CB0 + 0*CSZ, bh, 0, tid);  CPCOMMIT();
    attn_load_chunk(sb + CB0 + 1*CSZ, bh, 64, tid); CPCOMMIT();
    CPWAIT1(); __syncthreads();                // chunk 0 + Q ready

    uint32_t qf[2][4][4];
    #pragma unroll
    for (int mf=0; mf<2; mf++)
    #pragma unroll
    for (int ks=0; ks<4; ks++){
        uint32_t a = sb + (uint32_t)((w*32 + mf*16 + (lane&15))*72 + ks*16 + (lane>>4)*8)*2;
        LDSM4(qf[mf][ks][0],qf[mf][ks][1],qf[mf][ks][2],qf[mf][ks][3], a);
    }

    float Of[2][8][4];
    #pragma unroll
    for (int mf=0; mf<2; mf++)
        #pragma unroll
        for (int i=0;i<8;i++){ Of[mf][i][0]=Of[mf][i][1]=Of[mf][i][2]=Of[mf][i][3]=0.f; }
    float ls[2][2] = {{0.f,0.f},{0.f,0.f}};
    const float* bp00 = bias + (size_t)(q0 + w*32 + g) * L_;

    #pragma unroll 1
    for (int ch = 0; ch < 32; ch++){
        if (ch + 2 < 32){
            attn_load_chunk(sb + CB0 + (uint32_t)((ch+2)%3)*CSZ, bh, (ch+2)*64, tid);
            CPCOMMIT();
        }
        const uint32_t kb = sb + CB0 + (uint32_t)(ch%3)*CSZ;

        float sacc[2][8][4];
        #pragma unroll
        for (int mf=0; mf<2; mf++)
            #pragma unroll
            for (int i=0;i<8;i++){ sacc[mf][i][0]=sacc[mf][i][1]=sacc[mf][i][2]=sacc[mf][i][3]=0.f; }
        #pragma unroll
        for (int ks=0; ks<4; ks++){
            #pragma unroll
            for (int nf2=0; nf2<4; nf2++){
                uint32_t a = kb + (uint32_t)((nf2*16 + (lane&7) + ((lane>>4)<<3))*72
                                             + ks*16 + (((lane>>3)&1)<<3))*2;
                uint32_t b0,b1,b2,b3;
                LDSM4(b0,b1,b2,b3, a);
                #pragma unroll
                for (int mf=0; mf<2; mf++){
                    MMA(sacc[mf][2*nf2],   qf[mf][ks], b0,b1);
                    MMA(sacc[mf][2*nf2+1], qf[mf][ks], b2,b3);
                }
            }
        }
        const int k0 = ch*64;
        #pragma unroll
        for (int mf=0; mf<2; mf++){            // softmax (bounded scores)
            const float* bp = bp00 + (size_t)(mf*16)*L_;
            #pragma unroll
            for (int nf=0; nf<8; nf++){
                float2 bb0 = *(const float2*)(bp + k0 + nf*8 + 2*c);
                float2 bb1 = *(const float2*)(bp + 8*L_ + k0 + nf*8 + 2*c);
                sacc[mf][nf][0] = __expf(sacc[mf][nf][0] + bb0.x);
                sacc[mf][nf][1] = __expf(sacc[mf][nf][1] + bb0.y);
                sacc[mf][nf][2] = __expf(sacc[mf][nf][2] + bb1.x);
                sacc[mf][nf][3] = __expf(sacc[mf][nf][3] + bb1.y);
                ls[mf][0] += sacc[mf][nf][0] + sacc[mf][nf][1];
                ls[mf][1] += sacc[mf][nf][2] + sacc[mf][nf][3];
            }
        }
        #pragma unroll
        for (int ks=0; ks<4; ks++){            // O += P V
            uint32_t pa[2][4];
            #pragma unroll
            for (int mf=0; mf<2; mf++){
                pa[mf][0] = packh2(sacc[mf][2*ks][0],   sacc[mf][2*ks][1]);
                pa[mf][1] = packh2(sacc[mf][2*ks][2],   sacc[mf][2*ks][3]);
                pa[mf][2] = packh2(sacc[mf][2*ks+1][0], sacc[mf][2*ks+1][1]);
                pa[mf][3] = packh2(sacc[mf][2*ks+1][2], sacc[mf][2*ks+1][3]);
            }
            #pragma unroll
            for (int nf2=0; nf2<4; nf2++){
                uint32_t ro = (uint32_t)((nf2*16 + (lane&7) + ((lane>>4)<<3))*72
                                         + ks*16 + (((lane>>3)&1)<<3))*2;
                uint32_t h0,h1,h2,h3;
                LDSM4(h0,h1,h2,h3, kb + 9216 + ro);
                #pragma unroll
                for (int mf=0; mf<2; mf++){
                    MMA(Of[mf][2*nf2],   pa[mf], h0,h1);
                    MMA(Of[mf][2*nf2+1], pa[mf], h2,h3);
                }
            }
        }
        if (ch < 31){
            if (ch < 30) CPWAIT1(); else CPWAIT0();
            __syncthreads();
        }
    }

    const int b = bh >> 4, h = bh & 15;
    #pragma unroll
    for (int mf=0; mf<2; mf++){
        float l0s = ls[mf][0], l1s = ls[mf][1];
        l0s += __shfl_xor_sync(0xffffffffu, l0s, 1);
        l0s += __shfl_xor_sync(0xffffffffu, l0s, 2);
        l1s += __shfl_xor_sync(0xffffffffu, l1s, 1);
        l1s += __shfl_xor_sync(0xffffffffu, l1s, 2);
        const float i0 = 1.f/l0s, i1 = 1.f/l1s;
        const int lr = q0 + w*32 + mf*16 + g;
        #pragma unroll
        for (int nf=0; nf<8; nf++){
            int col = h*64 + nf*8 + 2*c;
            size_t o0 = ((size_t)b*L_ + lr)*C_ + col;
            size_t o1 = o0 + (size_t)8*C_;
            *(__half2*)&g_aoh[o0] = __floats2half2_rn(Of[mf][nf][0]*i0, Of[mf][nf][1]*i0);
            *(__half2*)&g_aoh[o1] = __floats2half2_rn(Of[mf][nf][2]*i1, Of[mf][nf][3]*i1);
        }
    }
}

// ---------------------------------------------------------------------------
extern "C" void kernel_launch(void* const* d_in, const int* in_sizes, int n_in,
                              void* d_out, int out_size)
{
    (void)in_sizes; (void)n_in; (void)out_size;
    const float* x         = (const float*)d_in[0];
    const float* attn_bias = (const float*)d_in[1];
    const float* w_qkv     = (const float*)d_in[2];
    const float* q_bias    = (const float*)d_in[3];
    const float* v_bias    = (const float*)d_in[4];
    const float* scale_mul = (const float*)d_in[5];
    const float* w_proj    = (const float*)d_in[6];
    const float* b_proj    = (const float*)d_in[7];
    float* out = (float*)d_out;

    const int GEMM_SMEM = 61440;   // 3 stages x 20480 (also fits 128x136 fp16 transpose)
    const int ATT_SMEM  = 73728;   // Q 18432 + 3 x 18432
    cudaFuncSetAttribute(gemm_mma<0>, cudaFuncAttributeMaxDynamicSharedMemorySize, GEMM_SMEM);
    cudaFuncSetAttribute(gemm_mma<1>, cudaFuncAttributeMaxDynamicSharedMemorySize, GEMM_SMEM);
    cudaFuncSetAttribute(attn_mma,    cudaFuncAttributeMaxDynamicSharedMemorySize, ATT_SMEM);

    // 0) convert fp32 inputs to fp16 in one launch
    const int NCVT = SEG0 + SEG1 + SEG2;
    cvt_all<<<(NCVT + 255)/256, 256>>>(x, w_qkv, w_proj);

    // 1) QKV projection + fused q/k L2-norm + fused V transpose
    gemm_mma<0><<<dim3(3*C_/128, M_/128), 256, GEMM_SMEM>>>(q_bias, v_bias, scale_mul, nullptr);

    // 2) fused attention
    attn_mma<<<dim3(L_/128, BH_), 128, ATT_SMEM>>>(attn_bias);

    // 3) output projection
    gemm_mma<1><<<dim3(C_/128, M_/128), 256, GEMM_SMEM>>>(b_proj, nullptr, nullptr, out);
}